// round 15
// baseline (speedup 1.0000x reference)
#include <cuda_runtime.h>
#include <cuda_fp16.h>
#include <math.h>
#include <stdint.h>

// Problem constants
#define B_   64
#define T_   32
#define H_   768
#define E_   8
#define NB_  2
#define DFF_ 3072
#define NBEAM 128

// Output packing offsets (float32 concatenation in tuple order)
#define OUT_MAIN 0
#define OUT_BS   (NBEAM * T_ * H_)
#define OUT_RT   (OUT_BS + NBEAM)
#define OUT_BI   (OUT_RT + NBEAM)
#define OUT_LOSS (OUT_BI + NBEAM)

// Scratch (device globals — allocation-free)
__device__ float g_logits[B_ * E_];
__device__ float g_weight[NBEAM];
__device__ int   g_expert[NBEAM];
__device__ int   g_perm[NBEAM];
__device__ int   g_off[E_ + 1];
__device__ __align__(16) __half g_xh[(size_t)B_ * T_ * H_];       // fp16 x
__device__ __align__(16) __half g_w1h[(size_t)E_ * DFF_ * H_];    // fp16 w1
__device__ __align__(16) __half g_w2h[(size_t)E_ * H_ * DFF_];    // fp16 w2
__device__ __align__(16) __half g_hh[(size_t)NBEAM * T_ * DFF_];  // fp16 h

// ---------------------------------------------------------------------------
// helpers
// ---------------------------------------------------------------------------
__device__ __forceinline__ uint32_t smem_u32(const void* p) {
    uint32_t a;
    asm("{ .reg .u64 t; cvta.to.shared.u64 t, %1; cvt.u32.u64 %0, t; }"
        : "=r"(a) : "l"(p));
    return a;
}

__device__ __forceinline__ void cp16(uint32_t smem_addr, const void* gptr) {
    asm volatile("cp.async.cg.shared.global [%0], [%1], 16;"
                 :: "r"(smem_addr), "l"(gptr));
}
#define CP_COMMIT() asm volatile("cp.async.commit_group;" ::: "memory")
#define CP_WAIT1()  asm volatile("cp.async.wait_group 1;" ::: "memory")

__device__ __forceinline__ void ldsm4(uint32_t* r, uint32_t addr) {
    asm volatile("ldmatrix.sync.aligned.m8n8.x4.shared.b16 {%0,%1,%2,%3}, [%4];"
        : "=r"(r[0]), "=r"(r[1]), "=r"(r[2]), "=r"(r[3]) : "r"(addr));
}

// fp16 MMA, fp32 accumulate
__device__ __forceinline__ void mma16816(float* c, const uint32_t* a, const uint32_t* b) {
    asm volatile(
        "mma.sync.aligned.m16n8k16.row.col.f32.f16.f16.f32 "
        "{%0,%1,%2,%3}, {%4,%5,%6,%7}, {%8,%9}, {%0,%1,%2,%3};"
        : "+f"(c[0]), "+f"(c[1]), "+f"(c[2]), "+f"(c[3])
        : "r"(a[0]), "r"(a[1]), "r"(a[2]), "r"(a[3]), "r"(b[0]), "r"(b[1]));
}

__device__ __forceinline__ float gelu_exact(float v) {
    return 0.5f * v * (1.0f + erff(v * 0.70710678118654752f));
}

__device__ __forceinline__ uint32_t pack_h2(float a, float b) {
    __half2 h = __floats2half2_rn(a, b);
    return *(uint32_t*)&h;
}

// ---------------------------------------------------------------------------
// prep: fp32 -> fp16.  which: 0 -> g_xh (+zero g_logits), 1 -> g_w1h, 2 -> g_w2h
// ---------------------------------------------------------------------------
__global__ void prep_h_kernel(const float* __restrict__ src, int which, int n4)
{
    int i = blockIdx.x * blockDim.x + threadIdx.x;
    if (which == 0 && i < B_ * E_) g_logits[i] = 0.f;
    if (i >= n4) return;
    __half* dst = (which == 0) ? g_xh : (which == 1) ? g_w1h : g_w2h;
    float4 v = ((const float4*)src)[i];
    uint2 o;
    o.x = pack_h2(v.x, v.y);
    o.y = pack_h2(v.z, v.w);
    ((uint2*)dst)[i] = o;
}

// ---------------------------------------------------------------------------
// gating, stage 1: partial logits via atomicAdd.  grid (B, 3) x 256
// ---------------------------------------------------------------------------
__global__ void gate_kernel(const float* __restrict__ x,
                            const float* __restrict__ gw)
{
    const int b = blockIdx.x;
    const int h = blockIdx.y * 256 + threadIdx.x;

    const float* xb = x + (size_t)b * T_ * H_ + h;
    float s = 0.f;
#pragma unroll 8
    for (int t = 0; t < T_; t++) s += xb[t * H_];
    float avg = s * (1.f / (float)T_);

    float part[E_];
#pragma unroll
    for (int e = 0; e < E_; e++) part[e] = avg * gw[e * H_ + h];

#pragma unroll
    for (int off = 16; off > 0; off >>= 1)
#pragma unroll
        for (int e = 0; e < E_; e++)
            part[e] += __shfl_down_sync(0xffffffffu, part[e], off);

    if ((threadIdx.x & 31) == 0) {
#pragma unroll
        for (int e = 0; e < E_; e++)
            atomicAdd(&g_logits[b * E_ + e], part[e]);
    }
}

// ---------------------------------------------------------------------------
// finalize: softmax, top-2, loss, tail outputs, expert grouping.  1 x 128
// ---------------------------------------------------------------------------
__global__ void finalize_kernel(float* __restrict__ out)
{
    const int tid = threadIdx.x;
    __shared__ float sc[B_][E_];
    __shared__ float simp[E_];

    if (tid < B_) {
        int b = tid;
        float lg[E_];
#pragma unroll
        for (int e = 0; e < E_; e++) lg[e] = g_logits[b * E_ + e];
        float m = lg[0];
#pragma unroll
        for (int e = 1; e < E_; e++) m = fmaxf(m, lg[e]);
        float s = 0.f;
#pragma unroll
        for (int e = 0; e < E_; e++) { lg[e] = expf(lg[e] - m); s += lg[e]; }
        float inv = 1.f / s;
        float v0 = -1.f, v1 = -1.f; int i0 = 0, i1 = 0;
#pragma unroll
        for (int e = 0; e < E_; e++) {
            float v = lg[e] * inv;
            sc[b][e] = v;
            if (v > v0)      { v1 = v0; i1 = i0; v0 = v; i0 = e; }
            else if (v > v1) { v1 = v;  i1 = e; }
        }
        out[OUT_BS + 2 * b]     = v0;
        out[OUT_BS + 2 * b + 1] = v1;
        out[OUT_RT + 2 * b]     = (float)i0;
        out[OUT_RT + 2 * b + 1] = (float)i1;
        g_weight[2 * b] = v0;  g_weight[2 * b + 1] = v1;
        g_expert[2 * b] = i0;  g_expert[2 * b + 1] = i1;
    }
    out[OUT_BI + tid] = (float)tid;
    __syncthreads();

    if (tid < E_) {
        float s = 0.f;
        for (int b = 0; b < B_; b++) s += sc[b][tid];
        simp[tid] = s;
    }
    __syncthreads();

    if (tid == 0) {
        float mean = 0.f;
#pragma unroll
        for (int e = 0; e < E_; e++) mean += simp[e];
        mean *= (1.f / (float)E_);
        float var = 0.f;
#pragma unroll
        for (int e = 0; e < E_; e++) { float d = simp[e] - mean; var += d * d; }
        var *= (1.f / (float)(E_ - 1));
        out[OUT_LOSS] = var / (mean * mean);
        int pos = 0;
        for (int e = 0; e < E_; e++) {
            g_off[e] = pos;
            for (int bm = 0; bm < NBEAM; bm++)
                if (g_expert[bm] == e) g_perm[pos++] = bm;
        }
        g_off[E_] = pos;
    }
}

// ---------------------------------------------------------------------------
// fp16 GEMM core pieces.  STR_H = 40 halves (80 B rows, conflict-free ldsm)
// ---------------------------------------------------------------------------
#define BKT 32
#define STR_H 40

#define KTILE_COMPUTE(bsel, ASTG_, BSTG_) do {                                 \
    _Pragma("unroll")                                                          \
    for (int ks = 0; ks < 2; ks++) {                                           \
        uint32_t _ao = a_base + (bsel) * (ASTG_) + ks * 32;                    \
        uint32_t _bo = b_base + (bsel) * (BSTG_) + ks * 32;                    \
        uint32_t ar0[4], ar1[4];                                               \
        ldsm4(ar0, _ao);                                                       \
        ldsm4(ar1, _ao + 16 * STR_H * 2);                                      \
        uint32_t br[4][4];                                                     \
        _Pragma("unroll")                                                      \
        for (int jj = 0; jj < 4; jj++)                                         \
            ldsm4(br[jj], _bo + jj * 16 * STR_H * 2);                          \
        _Pragma("unroll")                                                      \
        for (int jj = 0; jj < 4; jj++) {                                       \
            uint32_t b0[2] = { br[jj][0], br[jj][1] };                         \
            uint32_t b1[2] = { br[jj][2], br[jj][3] };                         \
            mma16816(acc[0][2 * jj],     ar0, b0);                             \
            mma16816(acc[1][2 * jj],     ar1, b0);                             \
            mma16816(acc[0][2 * jj + 1], ar0, b1);                             \
            mma16816(acc[1][2 * jj + 1], ar1, b1);                             \
        }                                                                      \
    }                                                                          \
} while (0)

// ======================= GEMM1: 128x128, 256 thr, 3-stage ==================
#define G1_BM 128
#define G1_ASTG (G1_BM * STR_H * 2u)          // 10240
#define G1_BSTG (128 * STR_H * 2u)            // 10240
#define G1_SMEM (3u * (G1_ASTG + G1_BSTG))    // 61440

// staging (256 thr): r0 = tid>>2 (0..63), c8 = (tid&3)*8 halves
#define G1_PREFETCH(psel, koff) do {                                           \
    uint32_t _ao = a_spT + (psel) * G1_ASTG;                                   \
    uint32_t _bo = b_spT + (psel) * G1_BSTG;                                   \
    cp16(_ao,                  agp[0] + (koff));                               \
    cp16(_ao + 64 * STR_H * 2, agp[1] + (koff));                               \
    cp16(_bo,                  bgp[0] + (koff));                               \
    cp16(_bo + 64 * STR_H * 2, bgp[1] + (koff));                               \
} while (0)

// h = gelu(x @ W1^T + b1) -> fp16 g_hh.  grid (24, E, 32)
__global__ void __launch_bounds__(256, 2)
gemm1_kernel(const float* __restrict__ bias)
{
    const int e = blockIdx.y;
    const int cnt = g_off[e + 1] - g_off[e];
    const int chunk = blockIdx.z;
    if (chunk * 4 >= cnt) return;
    const int m0 = blockIdx.x * G1_BM;

    extern __shared__ __align__(16) char smem[];
    const uint32_t a_sp0 = smem_u32(smem);
    const uint32_t b_sp0 = a_sp0 + 3 * G1_ASTG;

    const int tid = threadIdx.x;
    const int wid = tid >> 5, lane = tid & 31;
    const int wm = wid >> 1, wn = wid & 1;
    const int lg = lane >> 2, lt = lane & 3;

    int beamv[4];
#pragma unroll
    for (int j = 0; j < 4; j++) {
        int idx = chunk * 4 + j;
        beamv[j] = (idx < cnt) ? g_perm[g_off[e] + idx] : -1;
    }

    const int r0 = tid >> 2, c8 = (tid & 3) * 8;
    const __half* agp[2];
    const __half* bgp[2];
    agp[0] = g_w1h + (size_t)e * DFF_ * H_ + (size_t)(m0 + r0) * H_ + c8;
    agp[1] = agp[0] + (size_t)64 * H_;
#pragma unroll
    for (int t = 0; t < 2; t++) {
        int tok = r0 + 64 * t;
        int slot = tok >> 5, tt = tok & 31;
        int bm = beamv[slot]; if (bm < 0) bm = beamv[0];
        bgp[t] = g_xh + ((size_t)(bm >> 1) * T_ + tt) * H_ + c8;
    }
    const uint32_t a_spT = a_sp0 + (uint32_t)(r0 * STR_H + c8) * 2u;
    const uint32_t b_spT = b_sp0 + (uint32_t)(r0 * STR_H + c8) * 2u;

    const uint32_t a_base = a_sp0
        + (uint32_t)(((wm * 32 + (lane & 15)) * STR_H + ((lane >> 4) << 3)) << 1);
    const uint32_t b_base = b_sp0
        + (uint32_t)(((wn * 64 + ((lane >> 4) << 3) + (lane & 7)) * STR_H
                      + (((lane >> 3) & 1) << 3)) << 1);

    const int KT = H_ / BKT;   // 24

    G1_PREFETCH(0, 0);
    CP_COMMIT();
    G1_PREFETCH(1, BKT);
    CP_COMMIT();

    float acc[2][8][4];
#pragma unroll
    for (int i = 0; i < 2; i++)
#pragma unroll
        for (int j = 0; j < 8; j++)
#pragma unroll
            for (int r = 0; r < 4; r++) acc[i][j][r] = 0.f;

    int bsel = 0, psel = 2;
#pragma unroll 1
    for (int kt = 0; kt < KT; kt++) {
        CP_WAIT1();
        __syncthreads();
        if (kt + 2 < KT) G1_PREFETCH(psel, (kt + 2) * BKT);
        CP_COMMIT();
        KTILE_COMPUTE(bsel, G1_ASTG, G1_BSTG);
        bsel = (bsel == 2) ? 0 : bsel + 1;
        psel = (psel == 2) ? 0 : psel + 1;
    }

    // epilogue: gelu(+bias) -> fp16
#pragma unroll
    for (int i = 0; i < 2; i++) {
        int rr0 = wm * 32 + i * 16 + lg, rr1 = rr0 + 8;
        int gm0 = m0 + rr0, gm1 = m0 + rr1;
        float bi0 = bias[e * DFF_ + gm0];
        float bi1 = bias[e * DFF_ + gm1];
#pragma unroll
        for (int j = 0; j < 8; j++) {
            int tok = wn * 64 + j * 8 + lt * 2;
            int bm = beamv[tok >> 5];
            if (bm < 0) continue;
            int tt = tok & 31;
            __half* p = g_hh + ((size_t)bm * T_ + tt) * DFF_;
            p[gm0]        = __float2half_rn(gelu_exact(acc[i][j][0] + bi0));
            p[DFF_ + gm0] = __float2half_rn(gelu_exact(acc[i][j][1] + bi0));
            p[gm1]        = __float2half_rn(gelu_exact(acc[i][j][2] + bi1));
            p[DFF_ + gm1] = __float2half_rn(gelu_exact(acc[i][j][3] + bi1));
        }
    }
}

// ============ GEMM2 fused: 64x128, 128 thr (4 warps 2x2), 3-stage ==========
#define G2_BM 64
#define G2_ASTG (G2_BM * STR_H * 2u)          // 5120
#define G2_BSTG (128 * STR_H * 2u)            // 10240
#define G2_SMEM (3u * (G2_ASTG + G2_BSTG))    // 46080

// staging (128 thr): r0 = tid>>2 (0..31), c8 = (tid&3)*8 halves
#define G2_PREFETCH(psel, koff) do {                                           \
    uint32_t _ao = a_spT + (psel) * G2_ASTG;                                   \
    uint32_t _bo = b_spT + (psel) * G2_BSTG;                                   \
    cp16(_ao,                  agp[0] + (koff));                               \
    cp16(_ao + 32 * STR_H * 2, agp[1] + (koff));                               \
    _Pragma("unroll")                                                          \
    for (int t = 0; t < 4; t++)                                                \
        cp16(_bo + t * (32 * STR_H * 2), bgp[t] + (koff));                     \
} while (0)

// out = (h @ W2^T + b2) * wgt, written directly.  grid (12, E, 32)
__global__ void __launch_bounds__(128, 4)
gemm2_kernel(const float* __restrict__ bias, float* __restrict__ out)
{
    const int e = blockIdx.y;
    const int cnt = g_off[e + 1] - g_off[e];
    const int chunk = blockIdx.z;
    if (chunk * 4 >= cnt) return;
    const int m0 = blockIdx.x * G2_BM;

    extern __shared__ __align__(16) char smem[];
    const uint32_t a_sp0 = smem_u32(smem);
    const uint32_t b_sp0 = a_sp0 + 3 * G2_ASTG;

    const int tid = threadIdx.x;
    const int wid = tid >> 5, lane = tid & 31;
    const int wm = wid >> 1, wn = wid & 1;
    const int lg = lane >> 2, lt = lane & 3;

    int beamv[4];
#pragma unroll
    for (int j = 0; j < 4; j++) {
        int idx = chunk * 4 + j;
        beamv[j] = (idx < cnt) ? g_perm[g_off[e] + idx] : -1;
    }

    const int r0 = tid >> 2, c8 = (tid & 3) * 8;
    const __half* agp[2];
    const __half* bgp[4];
    agp[0] = g_w2h + (size_t)e * H_ * DFF_ + (size_t)(m0 + r0) * DFF_ + c8;
    agp[1] = agp[0] + (size_t)32 * DFF_;
#pragma unroll
    for (int t = 0; t < 4; t++) {
        int tok = r0 + 32 * t;
        int slot = tok >> 5, tt = tok & 31;
        int bm = beamv[slot]; if (bm < 0) bm = beamv[0];
        bgp[t] = g_hh + ((size_t)bm * T_ + tt) * DFF_ + c8;
    }
    const uint32_t a_spT = a_sp0 + (uint32_t)(r0 * STR_H + c8) * 2u;
    const uint32_t b_spT = b_sp0 + (uint32_t)(r0 * STR_H + c8) * 2u;

    const uint32_t a_base = a_sp0
        + (uint32_t)(((wm * 32 + (lane & 15)) * STR_H + ((lane >> 4) << 3)) << 1);
    const uint32_t b_base = b_sp0
        + (uint32_t)(((wn * 64 + ((lane >> 4) << 3) + (lane & 7)) * STR_H
                      + (((lane >> 3) & 1) << 3)) << 1);

    const int KT = DFF_ / BKT;   // 96

    G2_PREFETCH(0, 0);
    CP_COMMIT();
    G2_PREFETCH(1, BKT);
    CP_COMMIT();

    float acc[2][8][4];
#pragma unroll
    for (int i = 0; i < 2; i++)
#pragma unroll
        for (int j = 0; j < 8; j++)
#pragma unroll
            for (int r = 0; r < 4; r++) acc[i][j][r] = 0.f;

    int bsel = 0, psel = 2;
#pragma unroll 1
    for (int kt = 0; kt < KT; kt++) {
        CP_WAIT1();
        __syncthreads();
        if (kt + 2 < KT) G2_PREFETCH(psel, (kt + 2) * BKT);
        CP_COMMIT();
        KTILE_COMPUTE(bsel, G2_ASTG, G2_BSTG);
        bsel = (bsel == 2) ? 0 : bsel + 1;
        psel = (psel == 2) ? 0 : psel + 1;
    }

    // fused epilogue: (acc + b2) * wgt -> out
#pragma unroll
    for (int i = 0; i < 2; i++) {
        int rr0 = wm * 32 + i * 16 + lg, rr1 = rr0 + 8;
        int gm0 = m0 + rr0, gm1 = m0 + rr1;
        float bi0 = bias[e * H_ + gm0];
        float bi1 = bias[e * H_ + gm1];
#pragma unroll
        for (int j = 0; j < 8; j++) {
            int tok = wn * 64 + j * 8 + lt * 2;
            int bm = beamv[tok >> 5];
            if (bm < 0) continue;
            int tt = tok & 31;
            float w = g_weight[bm];
            float* p = out + OUT_MAIN + ((size_t)bm * T_ + tt) * H_;
            p[gm0]      = (acc[i][j][0] + bi0) * w;
            p[H_ + gm0] = (acc[i][j][1] + bi0) * w;
            p[gm1]      = (acc[i][j][2] + bi1) * w;
            p[H_ + gm1] = (acc[i][j][3] + bi1) * w;
        }
    }
}

// ---------------------------------------------------------------------------
extern "C" void kernel_launch(void* const* d_in, const int* in_sizes, int n_in,
                              void* d_out, int out_size)
{
    (void)in_sizes; (void)n_in; (void)out_size;
    const float* x      = (const float*)d_in[0];
    const float* gate_w = (const float*)d_in[1];
    const float* w1     = (const float*)d_in[2];
    const float* b1     = (const float*)d_in[3];
    const float* w2     = (const float*)d_in[4];
    const float* b2     = (const float*)d_in[5];
    float* out = (float*)d_out;

    cudaFuncSetAttribute(gemm1_kernel,
        cudaFuncAttributeMaxDynamicSharedMemorySize, G1_SMEM);
    cudaFuncSetAttribute(gemm2_kernel,
        cudaFuncAttributeMaxDynamicSharedMemorySize, G2_SMEM);

    const int NX4 = B_ * T_ * H_ / 4;          // 393216
    const int NW4 = E_ * DFF_ * H_ / 4;        // 4718592

    prep_h_kernel<<<(NX4 + 255) / 256, 256>>>(x, 0, NX4);
    prep_h_kernel<<<(NW4 + 255) / 256, 256>>>(w1, 1, NW4);
    prep_h_kernel<<<(NW4 + 255) / 256, 256>>>(w2, 2, NW4);
    gate_kernel<<<dim3(B_, 3), 256>>>(x, gate_w);
    finalize_kernel<<<1, 128>>>(out);
    gemm1_kernel<<<dim3(DFF_ / G1_BM, E_, 32), 256, G1_SMEM>>>(b1);
    gemm2_kernel<<<dim3(H_ / G2_BM, E_, 32), 128, G2_SMEM>>>(b2, out);
}

// round 16
// speedup vs baseline: 1.0318x; 1.0318x over previous
#include <cuda_runtime.h>
#include <cuda_fp16.h>
#include <math.h>
#include <stdint.h>

// Problem constants
#define B_   64
#define T_   32
#define H_   768
#define E_   8
#define NB_  2
#define DFF_ 3072
#define NBEAM 128
#define SPLIT 2

// Output packing offsets (float32 concatenation in tuple order)
#define OUT_MAIN 0
#define OUT_BS   (NBEAM * T_ * H_)
#define OUT_RT   (OUT_BS + NBEAM)
#define OUT_BI   (OUT_RT + NBEAM)
#define OUT_LOSS (OUT_BI + NBEAM)

// Scratch (device globals — allocation-free)
__device__ float g_logits[B_ * E_];
__device__ float g_weight[NBEAM];
__device__ int   g_expert[NBEAM];
__device__ int   g_perm[NBEAM];
__device__ int   g_off[E_ + 1];
__device__ __align__(16) __half g_xh[(size_t)B_ * T_ * H_];       // fp16 x
__device__ __align__(16) __half g_w1h[(size_t)E_ * DFF_ * H_];    // fp16 w1
__device__ __align__(16) __half g_w2h[(size_t)E_ * H_ * DFF_];    // fp16 w2
__device__ __align__(16) __half g_hh[(size_t)NBEAM * T_ * DFF_];  // fp16 h
__device__ float g_part[(size_t)SPLIT * NBEAM * T_ * H_];         // fp32 partials

// ---------------------------------------------------------------------------
// helpers
// ---------------------------------------------------------------------------
__device__ __forceinline__ uint32_t smem_u32(const void* p) {
    uint32_t a;
    asm("{ .reg .u64 t; cvta.to.shared.u64 t, %1; cvt.u32.u64 %0, t; }"
        : "=r"(a) : "l"(p));
    return a;
}

__device__ __forceinline__ void cp16(uint32_t smem_addr, const void* gptr) {
    asm volatile("cp.async.cg.shared.global [%0], [%1], 16;"
                 :: "r"(smem_addr), "l"(gptr));
}
#define CP_COMMIT() asm volatile("cp.async.commit_group;" ::: "memory")
#define CP_WAIT0()  asm volatile("cp.async.wait_group 0;" ::: "memory")

__device__ __forceinline__ void ldsm4(uint32_t* r, uint32_t addr) {
    asm volatile("ldmatrix.sync.aligned.m8n8.x4.shared.b16 {%0,%1,%2,%3}, [%4];"
        : "=r"(r[0]), "=r"(r[1]), "=r"(r[2]), "=r"(r[3]) : "r"(addr));
}

// fp16 MMA, fp32 accumulate: D(16x8) += A(16x16) * B(16x8)
__device__ __forceinline__ void mma16816(float* c, const uint32_t* a, const uint32_t* b) {
    asm volatile(
        "mma.sync.aligned.m16n8k16.row.col.f32.f16.f16.f32 "
        "{%0,%1,%2,%3}, {%4,%5,%6,%7}, {%8,%9}, {%0,%1,%2,%3};"
        : "+f"(c[0]), "+f"(c[1]), "+f"(c[2]), "+f"(c[3])
        : "r"(a[0]), "r"(a[1]), "r"(a[2]), "r"(a[3]), "r"(b[0]), "r"(b[1]));
}

__device__ __forceinline__ float gelu_exact(float v) {
    return 0.5f * v * (1.0f + erff(v * 0.70710678118654752f));
}

__device__ __forceinline__ uint32_t pack_h2(float a, float b) {
    __half2 h = __floats2half2_rn(a, b);
    return *(uint32_t*)&h;
}

// ---------------------------------------------------------------------------
// prep: fp32 -> fp16 conversions.  which: 0 -> g_xh (+zero g_logits),
// 1 -> g_w1h, 2 -> g_w2h.  i indexes float4 (4 elements).
// ---------------------------------------------------------------------------
__global__ void prep_h_kernel(const float* __restrict__ src, int which, int n4)
{
    int i = blockIdx.x * blockDim.x + threadIdx.x;
    if (which == 0 && i < B_ * E_) g_logits[i] = 0.f;
    if (i >= n4) return;
    __half* dst = (which == 0) ? g_xh : (which == 1) ? g_w1h : g_w2h;
    float4 v = ((const float4*)src)[i];
    uint2 o;
    o.x = pack_h2(v.x, v.y);
    o.y = pack_h2(v.z, v.w);
    ((uint2*)dst)[i] = o;
}

// ---------------------------------------------------------------------------
// gating, stage 1: partial logits via atomicAdd.  grid (B, 3) x 256
// ---------------------------------------------------------------------------
__global__ void gate_kernel(const float* __restrict__ x,
                            const float* __restrict__ gw)
{
    const int b = blockIdx.x;
    const int h = blockIdx.y * 256 + threadIdx.x;

    const float* xb = x + (size_t)b * T_ * H_ + h;
    float s = 0.f;
#pragma unroll 8
    for (int t = 0; t < T_; t++) s += xb[t * H_];
    float avg = s * (1.f / (float)T_);

    float part[E_];
#pragma unroll
    for (int e = 0; e < E_; e++) part[e] = avg * gw[e * H_ + h];

#pragma unroll
    for (int off = 16; off > 0; off >>= 1)
#pragma unroll
        for (int e = 0; e < E_; e++)
            part[e] += __shfl_down_sync(0xffffffffu, part[e], off);

    if ((threadIdx.x & 31) == 0) {
#pragma unroll
        for (int e = 0; e < E_; e++)
            atomicAdd(&g_logits[b * E_ + e], part[e]);
    }
}

// ---------------------------------------------------------------------------
// finalize: softmax, top-2, loss, tail outputs, expert grouping.  1 x 128
// ---------------------------------------------------------------------------
__global__ void finalize_kernel(float* __restrict__ out)
{
    const int tid = threadIdx.x;
    __shared__ float sc[B_][E_];
    __shared__ float simp[E_];

    if (tid < B_) {
        int b = tid;
        float lg[E_];
#pragma unroll
        for (int e = 0; e < E_; e++) lg[e] = g_logits[b * E_ + e];
        float m = lg[0];
#pragma unroll
        for (int e = 1; e < E_; e++) m = fmaxf(m, lg[e]);
        float s = 0.f;
#pragma unroll
        for (int e = 0; e < E_; e++) { lg[e] = expf(lg[e] - m); s += lg[e]; }
        float inv = 1.f / s;
        float v0 = -1.f, v1 = -1.f; int i0 = 0, i1 = 0;
#pragma unroll
        for (int e = 0; e < E_; e++) {
            float v = lg[e] * inv;
            sc[b][e] = v;
            if (v > v0)      { v1 = v0; i1 = i0; v0 = v; i0 = e; }
            else if (v > v1) { v1 = v;  i1 = e; }
        }
        out[OUT_BS + 2 * b]     = v0;
        out[OUT_BS + 2 * b + 1] = v1;
        out[OUT_RT + 2 * b]     = (float)i0;
        out[OUT_RT + 2 * b + 1] = (float)i1;
        g_weight[2 * b] = v0;  g_weight[2 * b + 1] = v1;
        g_expert[2 * b] = i0;  g_expert[2 * b + 1] = i1;
    }
    out[OUT_BI + tid] = (float)tid;
    __syncthreads();

    if (tid < E_) {
        float s = 0.f;
        for (int b = 0; b < B_; b++) s += sc[b][tid];
        simp[tid] = s;
    }
    __syncthreads();

    if (tid == 0) {
        float mean = 0.f;
#pragma unroll
        for (int e = 0; e < E_; e++) mean += simp[e];
        mean *= (1.f / (float)E_);
        float var = 0.f;
#pragma unroll
        for (int e = 0; e < E_; e++) { float d = simp[e] - mean; var += d * d; }
        var *= (1.f / (float)(E_ - 1));
        out[OUT_LOSS] = var / (mean * mean);
        int pos = 0;
        for (int e = 0; e < E_; e++) {
            g_off[e] = pos;
            for (int bm = 0; bm < NBEAM; bm++)
                if (g_expert[bm] == e) g_perm[pos++] = bm;
        }
        g_off[E_] = pos;
    }
}

// ---------------------------------------------------------------------------
// fp16 GEMM: CTA 128(M) x 128(N), BK=32 halves, 256 thr, 8 warps (4x2),
// warp tile 32x64 via m16n8k16.  All operands fp16; fp32 accum.
// 2-stage double buffer.  No cvt in mainloop.  (R14 geometry — measured best)
// ---------------------------------------------------------------------------
#define BM 128
#define BN 128
#define BKT 32
#define STR_H 40                  // halves; 80 B rows -> conflict-free ldsm
#define ASTG (BM * STR_H * 2u)    // 10240 B per stage
#define BSTG (BN * STR_H * 2u)    // 10240 B per stage
#define SMEM_BYTES (2u * (ASTG + BSTG))     // 40960

// staging: r0 = tid>>2 (0..63), c8 = (tid&3)*8 halves; rows r0 and r0+64.
#define PREFETCH(koff) do {                                                    \
    uint32_t _ao = a_spT + bsel_p * ASTG;                                      \
    uint32_t _bo = b_spT + bsel_p * BSTG;                                      \
    cp16(_ao,                     agp[0] + (koff));                            \
    cp16(_ao + 64 * STR_H * 2,    agp[1] + (koff));                            \
    cp16(_bo,                     bgp[0] + (koff));                            \
    cp16(_bo + 64 * STR_H * 2,    bgp[1] + (koff));                            \
} while (0)

#define KTILE_COMPUTE(bsel) do {                                               \
    _Pragma("unroll")                                                          \
    for (int ks = 0; ks < 2; ks++) {                                           \
        uint32_t _ao = a_base + (bsel) * ASTG + ks * 32;                       \
        uint32_t _bo = b_base + (bsel) * BSTG + ks * 32;                       \
        uint32_t ar0[4], ar1[4];                                               \
        ldsm4(ar0, _ao);                                                       \
        ldsm4(ar1, _ao + 16 * STR_H * 2);                                      \
        uint32_t br[4][4];                                                     \
        _Pragma("unroll")                                                      \
        for (int jj = 0; jj < 4; jj++)                                         \
            ldsm4(br[jj], _bo + jj * 16 * STR_H * 2);                          \
        _Pragma("unroll")                                                      \
        for (int jj = 0; jj < 4; jj++) {                                       \
            uint32_t b0[2] = { br[jj][0], br[jj][1] };                         \
            uint32_t b1[2] = { br[jj][2], br[jj][3] };                         \
            mma16816(acc[0][2 * jj],     ar0, b0);                             \
            mma16816(acc[1][2 * jj],     ar1, b0);                             \
            mma16816(acc[0][2 * jj + 1], ar0, b1);                             \
            mma16816(acc[1][2 * jj + 1], ar1, b1);                             \
        }                                                                      \
    }                                                                          \
} while (0)

// GEMM1: h = gelu(x @ W1^T + b1) -> fp16 g_hh.  grid (24, E, 32)
__global__ void __launch_bounds__(256, 2)
gemm1_kernel(const float* __restrict__ bias)
{
    const int e = blockIdx.y;
    const int cnt = g_off[e + 1] - g_off[e];
    const int chunk = blockIdx.z;
    if (chunk * 4 >= cnt) return;
    const int m0 = blockIdx.x * BM;

    extern __shared__ __align__(16) char smem[];
    const uint32_t a_sp0 = smem_u32(smem);
    const uint32_t b_sp0 = a_sp0 + 2 * ASTG;

    const int tid = threadIdx.x;
    const int wid = tid >> 5, lane = tid & 31;
    const int wm = wid >> 1, wn = wid & 1;
    const int lg = lane >> 2, lt = lane & 3;

    int beamv[4];
#pragma unroll
    for (int j = 0; j < 4; j++) {
        int idx = chunk * 4 + j;
        beamv[j] = (idx < cnt) ? g_perm[g_off[e] + idx] : -1;
    }

    const int r0 = tid >> 2, c8 = (tid & 3) * 8;
    const __half* agp[2];
    const __half* bgp[2];
    agp[0] = g_w1h + (size_t)e * DFF_ * H_ + (size_t)(m0 + r0) * H_ + c8;
    agp[1] = agp[0] + (size_t)64 * H_;
#pragma unroll
    for (int t = 0; t < 2; t++) {
        int tok = r0 + 64 * t;
        int slot = tok >> 5, tt = tok & 31;
        int bm = beamv[slot]; if (bm < 0) bm = beamv[0];
        bgp[t] = g_xh + ((size_t)(bm >> 1) * T_ + tt) * H_ + c8;
    }
    const uint32_t a_spT = a_sp0 + (uint32_t)(r0 * STR_H + c8) * 2u;
    const uint32_t b_spT = b_sp0 + (uint32_t)(r0 * STR_H + c8) * 2u;

    const uint32_t a_base = a_sp0
        + (uint32_t)(((wm * 32 + (lane & 15)) * STR_H + ((lane >> 4) << 3)) << 1);
    const uint32_t b_base = b_sp0
        + (uint32_t)(((wn * 64 + ((lane >> 4) << 3) + (lane & 7)) * STR_H
                      + (((lane >> 3) & 1) << 3)) << 1);

    const int KT = H_ / BKT;   // 24

    { int bsel_p = 0; PREFETCH(0); }
    CP_COMMIT();

    float acc[2][8][4];
#pragma unroll
    for (int i = 0; i < 2; i++)
#pragma unroll
        for (int j = 0; j < 8; j++)
#pragma unroll
            for (int r = 0; r < 4; r++) acc[i][j][r] = 0.f;

#pragma unroll 1
    for (int kt = 0; kt < KT; kt++) {
        CP_WAIT0();
        __syncthreads();
        if (kt + 1 < KT) {
            int bsel_p = (kt + 1) & 1;
            PREFETCH((kt + 1) * BKT);
        }
        CP_COMMIT();
        KTILE_COMPUTE(kt & 1);
    }

    // epilogue: gelu(+bias) -> fp16
#pragma unroll
    for (int i = 0; i < 2; i++) {
        int rr0 = wm * 32 + i * 16 + lg, rr1 = rr0 + 8;
        int gm0 = m0 + rr0, gm1 = m0 + rr1;
        float bi0 = bias[e * DFF_ + gm0];
        float bi1 = bias[e * DFF_ + gm1];
#pragma unroll
        for (int j = 0; j < 8; j++) {
            int tok = wn * 64 + j * 8 + lt * 2;
            int bm = beamv[tok >> 5];
            if (bm < 0) continue;
            int tt = tok & 31;
            __half* p = g_hh + ((size_t)bm * T_ + tt) * DFF_;
            p[gm0]        = __float2half_rn(gelu_exact(acc[i][j][0] + bi0));
            p[DFF_ + gm0] = __float2half_rn(gelu_exact(acc[i][j][1] + bi0));
            p[gm1]        = __float2half_rn(gelu_exact(acc[i][j][2] + bi1));
            p[DFF_ + gm1] = __float2half_rn(gelu_exact(acc[i][j][3] + bi1));
        }
    }
}

// GEMM2 split-K (SPLIT=2): partial = h @ W2^T -> fp32 g_part. grid (6, E, 32*SPLIT)
__global__ void __launch_bounds__(256, 2)
gemm2_kernel(void)
{
    const int e = blockIdx.y;
    const int cnt = g_off[e + 1] - g_off[e];
    const int chunk = blockIdx.z / SPLIT;
    const int split = blockIdx.z % SPLIT;
    if (chunk * 4 >= cnt) return;
    const int m0 = blockIdx.x * BM;
    const int k0 = split * (DFF_ / SPLIT);

    extern __shared__ __align__(16) char smem[];
    const uint32_t a_sp0 = smem_u32(smem);
    const uint32_t b_sp0 = a_sp0 + 2 * ASTG;

    const int tid = threadIdx.x;
    const int wid = tid >> 5, lane = tid & 31;
    const int wm = wid >> 1, wn = wid & 1;
    const int lg = lane >> 2, lt = lane & 3;

    int beamv[4];
#pragma unroll
    for (int j = 0; j < 4; j++) {
        int idx = chunk * 4 + j;
        beamv[j] = (idx < cnt) ? g_perm[g_off[e] + idx] : -1;
    }

    const int r0 = tid >> 2, c8 = (tid & 3) * 8;
    const __half* agp[2];
    const __half* bgp[2];
    agp[0] = g_w2h + (size_t)e * H_ * DFF_ + (size_t)(m0 + r0) * DFF_ + k0 + c8;
    agp[1] = agp[0] + (size_t)64 * DFF_;
#pragma unroll
    for (int t = 0; t < 2; t++) {
        int tok = r0 + 64 * t;
        int slot = tok >> 5, tt = tok & 31;
        int bm = beamv[slot]; if (bm < 0) bm = beamv[0];
        bgp[t] = g_hh + ((size_t)bm * T_ + tt) * DFF_ + k0 + c8;
    }
    const uint32_t a_spT = a_sp0 + (uint32_t)(r0 * STR_H + c8) * 2u;
    const uint32_t b_spT = b_sp0 + (uint32_t)(r0 * STR_H + c8) * 2u;

    const uint32_t a_base = a_sp0
        + (uint32_t)(((wm * 32 + (lane & 15)) * STR_H + ((lane >> 4) << 3)) << 1);
    const uint32_t b_base = b_sp0
        + (uint32_t)(((wn * 64 + ((lane >> 4) << 3) + (lane & 7)) * STR_H
                      + (((lane >> 3) & 1) << 3)) << 1);

    const int KT = (DFF_ / SPLIT) / BKT;   // 48

    { int bsel_p = 0; PREFETCH(0); }
    CP_COMMIT();

    float acc[2][8][4];
#pragma unroll
    for (int i = 0; i < 2; i++)
#pragma unroll
        for (int j = 0; j < 8; j++)
#pragma unroll
            for (int r = 0; r < 4; r++) acc[i][j][r] = 0.f;

#pragma unroll 1
    for (int kt = 0; kt < KT; kt++) {
        CP_WAIT0();
        __syncthreads();
        if (kt + 1 < KT) {
            int bsel_p = (kt + 1) & 1;
            PREFETCH((kt + 1) * BKT);
        }
        CP_COMMIT();
        KTILE_COMPUTE(kt & 1);
    }

    // epilogue: raw fp32 partials
#pragma unroll
    for (int i = 0; i < 2; i++) {
        int rr0 = wm * 32 + i * 16 + lg, rr1 = rr0 + 8;
        int gm0 = m0 + rr0, gm1 = m0 + rr1;
        float* pb = g_part + (size_t)split * NBEAM * T_ * H_;
#pragma unroll
        for (int j = 0; j < 8; j++) {
            int tok = wn * 64 + j * 8 + lt * 2;
            int bm = beamv[tok >> 5];
            if (bm < 0) continue;
            int tt = tok & 31;
            float* p = pb + ((size_t)bm * T_ + tt) * H_;
            p[gm0]      = acc[i][j][0];
            p[H_ + gm0] = acc[i][j][1];
            p[gm1]      = acc[i][j][2];
            p[H_ + gm1] = acc[i][j][3];
        }
    }
}

// Reduce: out = (sum of SPLIT partials + b2[e]) * wgt
__global__ void reduce_kernel(const float* __restrict__ b2, float* __restrict__ out)
{
    int i = blockIdx.x * blockDim.x + threadIdx.x;
    const int N4 = NBEAM * T_ * H_ / 4;
    if (i >= N4) return;
    int flat = i * 4;
    int beam = flat / (T_ * H_);
    int hh   = flat % H_;
    int e    = g_expert[beam];
    float wgt = g_weight[beam];
    const size_t PS = (size_t)NBEAM * T_ * H_;
    float4 s  = ((const float4*)g_part)[i];
    float4 p1 = ((const float4*)(g_part + PS))[i];
    float4 bbv = *(const float4*)(b2 + e * H_ + hh);
    float4 o;
    o.x = (s.x + p1.x + bbv.x) * wgt;
    o.y = (s.y + p1.y + bbv.y) * wgt;
    o.z = (s.z + p1.z + bbv.z) * wgt;
    o.w = (s.w + p1.w + bbv.w) * wgt;
    ((float4*)(out + OUT_MAIN))[i] = o;
}

// ---------------------------------------------------------------------------
extern "C" void kernel_launch(void* const* d_in, const int* in_sizes, int n_in,
                              void* d_out, int out_size)
{
    (void)in_sizes; (void)n_in; (void)out_size;
    const float* x      = (const float*)d_in[0];
    const float* gate_w = (const float*)d_in[1];
    const float* w1     = (const float*)d_in[2];
    const float* b1     = (const float*)d_in[3];
    const float* w2     = (const float*)d_in[4];
    const float* b2     = (const float*)d_in[5];
    float* out = (float*)d_out;

    // One-time setup (no device memory allocation; streams/events are host objects)
    static cudaStream_t sW1 = nullptr, sW2 = nullptr;
    static cudaEvent_t evRoot = nullptr, evW1 = nullptr, evW2 = nullptr;
    if (sW1 == nullptr) {
        cudaStreamCreateWithFlags(&sW1, cudaStreamNonBlocking);
        cudaStreamCreateWithFlags(&sW2, cudaStreamNonBlocking);
        cudaEventCreateWithFlags(&evRoot, cudaEventDisableTiming);
        cudaEventCreateWithFlags(&evW1, cudaEventDisableTiming);
        cudaEventCreateWithFlags(&evW2, cudaEventDisableTiming);
        cudaFuncSetAttribute(gemm1_kernel,
            cudaFuncAttributeMaxDynamicSharedMemorySize, SMEM_BYTES);
        cudaFuncSetAttribute(gemm2_kernel,
            cudaFuncAttributeMaxDynamicSharedMemorySize, SMEM_BYTES);
    }

    const int NX4 = B_ * T_ * H_ / 4;          // 393216
    const int NW4 = E_ * DFF_ * H_ / 4;        // 4718592

    // Fork: weight conversions on side streams, everything else on capture stream
    cudaEventRecord(evRoot, 0);
    cudaStreamWaitEvent(sW1, evRoot, 0);
    cudaStreamWaitEvent(sW2, evRoot, 0);

    prep_h_kernel<<<(NW4 + 255) / 256, 256, 0, sW1>>>(w1, 1, NW4);
    cudaEventRecord(evW1, sW1);
    prep_h_kernel<<<(NW4 + 255) / 256, 256, 0, sW2>>>(w2, 2, NW4);
    cudaEventRecord(evW2, sW2);

    prep_h_kernel<<<(NX4 + 255) / 256, 256>>>(x, 0, NX4);
    gate_kernel<<<dim3(B_, 3), 256>>>(x, gate_w);
    finalize_kernel<<<1, 128>>>(out);

    // Join w1 before GEMM1
    cudaStreamWaitEvent(0, evW1, 0);
    gemm1_kernel<<<dim3(DFF_ / BM, E_, 32), 256, SMEM_BYTES>>>(b1);

    // Join w2 before GEMM2 (prep_w2 overlapped with gate/finalize/gemm1)
    cudaStreamWaitEvent(0, evW2, 0);
    gemm2_kernel<<<dim3(H_ / BM, E_, 32 * SPLIT), 256, SMEM_BYTES>>>();
    reduce_kernel<<<(NBEAM * T_ * H_ / 4 + 255) / 256, 256>>>(b2, out);
}

// round 17
// speedup vs baseline: 1.0397x; 1.0076x over previous
#include <cuda_runtime.h>
#include <cuda_fp16.h>
#include <math.h>
#include <stdint.h>

// Problem constants
#define B_   64
#define T_   32
#define H_   768
#define E_   8
#define NB_  2
#define DFF_ 3072
#define NBEAM 128
#define SPLIT 2

// Output packing offsets (float32 concatenation in tuple order)
#define OUT_MAIN 0
#define OUT_BS   (NBEAM * T_ * H_)
#define OUT_RT   (OUT_BS + NBEAM)
#define OUT_BI   (OUT_RT + NBEAM)
#define OUT_LOSS (OUT_BI + NBEAM)

// Scratch (device globals — allocation-free)
__device__ float g_logits[B_ * E_];
__device__ float g_weight[NBEAM];
__device__ int   g_expert[NBEAM];
__device__ int   g_perm[NBEAM];
__device__ int   g_off[E_ + 1];
__device__ __align__(16) __half g_xh[(size_t)B_ * T_ * H_];       // fp16 x
__device__ __align__(16) __half g_w1h[(size_t)E_ * DFF_ * H_];    // fp16 w1
__device__ __align__(16) __half g_w2h[(size_t)E_ * H_ * DFF_];    // fp16 w2
__device__ __align__(16) __half g_hh[(size_t)NBEAM * T_ * DFF_];  // fp16 h
__device__ float g_part[(size_t)SPLIT * NBEAM * T_ * H_];         // fp32 partials

// ---------------------------------------------------------------------------
// helpers
// ---------------------------------------------------------------------------
__device__ __forceinline__ uint32_t smem_u32(const void* p) {
    uint32_t a;
    asm("{ .reg .u64 t; cvta.to.shared.u64 t, %1; cvt.u32.u64 %0, t; }"
        : "=r"(a) : "l"(p));
    return a;
}

__device__ __forceinline__ void cp16(uint32_t smem_addr, const void* gptr) {
    asm volatile("cp.async.cg.shared.global [%0], [%1], 16;"
                 :: "r"(smem_addr), "l"(gptr));
}
#define CP_COMMIT() asm volatile("cp.async.commit_group;" ::: "memory")
#define CP_WAIT0()  asm volatile("cp.async.wait_group 0;" ::: "memory")

__device__ __forceinline__ void ldsm4(uint32_t* r, uint32_t addr) {
    asm volatile("ldmatrix.sync.aligned.m8n8.x4.shared.b16 {%0,%1,%2,%3}, [%4];"
        : "=r"(r[0]), "=r"(r[1]), "=r"(r[2]), "=r"(r[3]) : "r"(addr));
}

// fp16 MMA, fp32 accumulate: D(16x8) += A(16x16) * B(16x8)
__device__ __forceinline__ void mma16816(float* c, const uint32_t* a, const uint32_t* b) {
    asm volatile(
        "mma.sync.aligned.m16n8k16.row.col.f32.f16.f16.f32 "
        "{%0,%1,%2,%3}, {%4,%5,%6,%7}, {%8,%9}, {%0,%1,%2,%3};"
        : "+f"(c[0]), "+f"(c[1]), "+f"(c[2]), "+f"(c[3])
        : "r"(a[0]), "r"(a[1]), "r"(a[2]), "r"(a[3]), "r"(b[0]), "r"(b[1]));
}

__device__ __forceinline__ float gelu_exact(float v) {
    return 0.5f * v * (1.0f + erff(v * 0.70710678118654752f));
}

__device__ __forceinline__ uint32_t pack_h2(float a, float b) {
    __half2 h = __floats2half2_rn(a, b);
    return *(uint32_t*)&h;
}

// ---------------------------------------------------------------------------
// prep: fp32 -> fp16 weight conversions.  which: 1 -> g_w1h, 2 -> g_w2h
// ---------------------------------------------------------------------------
__global__ void prep_h_kernel(const float* __restrict__ src, int which, int n4)
{
    int i = blockIdx.x * blockDim.x + threadIdx.x;
    if (i >= n4) return;
    __half* dst = (which == 1) ? g_w1h : g_w2h;
    float4 v = ((const float4*)src)[i];
    uint2 o;
    o.x = pack_h2(v.x, v.y);
    o.y = pack_h2(v.z, v.w);
    ((uint2*)dst)[i] = o;
}

// ---------------------------------------------------------------------------
// fused gate: per-batch block (64 blocks x 192 threads).
// Each thread owns 4 h-columns (float4):
//   - streams x[b,:,h4..h4+3] once: accumulates T-sum AND emits fp16 g_xh
//   - computes its logit contributions, block-reduces -> g_logits[b][:]
// No atomics, no zeroing, no separate prep_x pass.
// ---------------------------------------------------------------------------
__global__ void gate_fused_kernel(const float* __restrict__ x,
                                  const float* __restrict__ gw)
{
    const int b   = blockIdx.x;
    const int tid = threadIdx.x;        // 0..191
    const int h4  = tid * 4;            // 0..764

    const float* xb = x + (size_t)b * T_ * H_ + h4;
    __half* xh = g_xh + (size_t)b * T_ * H_ + h4;

    float s0 = 0.f, s1 = 0.f, s2 = 0.f, s3 = 0.f;
#pragma unroll 8
    for (int t = 0; t < T_; t++) {
        float4 v = *(const float4*)(xb + (size_t)t * H_);
        s0 += v.x; s1 += v.y; s2 += v.z; s3 += v.w;
        uint2 o;
        o.x = pack_h2(v.x, v.y);
        o.y = pack_h2(v.z, v.w);
        *(uint2*)(xh + (size_t)t * H_) = o;
    }
    const float inv_t = 1.f / (float)T_;
    s0 *= inv_t; s1 *= inv_t; s2 *= inv_t; s3 *= inv_t;

    float part[E_];
#pragma unroll
    for (int e = 0; e < E_; e++) {
        float4 g = *(const float4*)(gw + e * H_ + h4);
        part[e] = s0 * g.x + s1 * g.y + s2 * g.z + s3 * g.w;
    }

    // warp reduce (6 warps of 32)
#pragma unroll
    for (int off = 16; off > 0; off >>= 1)
#pragma unroll
        for (int e = 0; e < E_; e++)
            part[e] += __shfl_down_sync(0xffffffffu, part[e], off);

    __shared__ float sacc[6][E_];
    const int wid = tid >> 5, lane = tid & 31;
    if (lane == 0)
#pragma unroll
        for (int e = 0; e < E_; e++) sacc[wid][e] = part[e];
    __syncthreads();

    if (tid < E_) {
        float s = 0.f;
#pragma unroll
        for (int w = 0; w < 6; w++) s += sacc[w][tid];
        g_logits[b * E_ + tid] = s;     // full overwrite — no zeroing needed
    }
}

// ---------------------------------------------------------------------------
// finalize: softmax, top-2, loss, tail outputs, expert grouping.  1 x 128
// ---------------------------------------------------------------------------
__global__ void finalize_kernel(float* __restrict__ out)
{
    const int tid = threadIdx.x;
    __shared__ float sc[B_][E_];
    __shared__ float simp[E_];

    if (tid < B_) {
        int b = tid;
        float lg[E_];
#pragma unroll
        for (int e = 0; e < E_; e++) lg[e] = g_logits[b * E_ + e];
        float m = lg[0];
#pragma unroll
        for (int e = 1; e < E_; e++) m = fmaxf(m, lg[e]);
        float s = 0.f;
#pragma unroll
        for (int e = 0; e < E_; e++) { lg[e] = expf(lg[e] - m); s += lg[e]; }
        float inv = 1.f / s;
        float v0 = -1.f, v1 = -1.f; int i0 = 0, i1 = 0;
#pragma unroll
        for (int e = 0; e < E_; e++) {
            float v = lg[e] * inv;
            sc[b][e] = v;
            if (v > v0)      { v1 = v0; i1 = i0; v0 = v; i0 = e; }
            else if (v > v1) { v1 = v;  i1 = e; }
        }
        out[OUT_BS + 2 * b]     = v0;
        out[OUT_BS + 2 * b + 1] = v1;
        out[OUT_RT + 2 * b]     = (float)i0;
        out[OUT_RT + 2 * b + 1] = (float)i1;
        g_weight[2 * b] = v0;  g_weight[2 * b + 1] = v1;
        g_expert[2 * b] = i0;  g_expert[2 * b + 1] = i1;
    }
    out[OUT_BI + tid] = (float)tid;
    __syncthreads();

    if (tid < E_) {
        float s = 0.f;
        for (int b = 0; b < B_; b++) s += sc[b][tid];
        simp[tid] = s;
    }
    __syncthreads();

    if (tid == 0) {
        float mean = 0.f;
#pragma unroll
        for (int e = 0; e < E_; e++) mean += simp[e];
        mean *= (1.f / (float)E_);
        float var = 0.f;
#pragma unroll
        for (int e = 0; e < E_; e++) { float d = simp[e] - mean; var += d * d; }
        var *= (1.f / (float)(E_ - 1));
        out[OUT_LOSS] = var / (mean * mean);
        int pos = 0;
        for (int e = 0; e < E_; e++) {
            g_off[e] = pos;
            for (int bm = 0; bm < NBEAM; bm++)
                if (g_expert[bm] == e) g_perm[pos++] = bm;
        }
        g_off[E_] = pos;
    }
}

// ---------------------------------------------------------------------------
// fp16 GEMM: CTA 128(M) x 128(N), BK=32 halves, 256 thr, 8 warps (4x2),
// warp tile 32x64 via m16n8k16.  All operands fp16; fp32 accum.
// 2-stage double buffer.  (R14/R16 geometry — measured best.)
// ---------------------------------------------------------------------------
#define BM 128
#define BN 128
#define BKT 32
#define STR_H 40                  // halves; 80 B rows -> conflict-free ldsm
#define ASTG (BM * STR_H * 2u)    // 10240 B per stage
#define BSTG (BN * STR_H * 2u)    // 10240 B per stage
#define SMEM_BYTES (2u * (ASTG + BSTG))     // 40960

// staging: r0 = tid>>2 (0..63), c8 = (tid&3)*8 halves; rows r0 and r0+64.
#define PREFETCH(koff) do {                                                    \
    uint32_t _ao = a_spT + bsel_p * ASTG;                                      \
    uint32_t _bo = b_spT + bsel_p * BSTG;                                      \
    cp16(_ao,                     agp[0] + (koff));                            \
    cp16(_ao + 64 * STR_H * 2,    agp[1] + (koff));                            \
    cp16(_bo,                     bgp[0] + (koff));                            \
    cp16(_bo + 64 * STR_H * 2,    bgp[1] + (koff));                            \
} while (0)

#define KTILE_COMPUTE(bsel) do {                                               \
    _Pragma("unroll")                                                          \
    for (int ks = 0; ks < 2; ks++) {                                           \
        uint32_t _ao = a_base + (bsel) * ASTG + ks * 32;                       \
        uint32_t _bo = b_base + (bsel) * BSTG + ks * 32;                       \
        uint32_t ar0[4], ar1[4];                                               \
        ldsm4(ar0, _ao);                                                       \
        ldsm4(ar1, _ao + 16 * STR_H * 2);                                      \
        uint32_t br[4][4];                                                     \
        _Pragma("unroll")                                                      \
        for (int jj = 0; jj < 4; jj++)                                         \
            ldsm4(br[jj], _bo + jj * 16 * STR_H * 2);                          \
        _Pragma("unroll")                                                      \
        for (int jj = 0; jj < 4; jj++) {                                       \
            uint32_t b0[2] = { br[jj][0], br[jj][1] };                         \
            uint32_t b1[2] = { br[jj][2], br[jj][3] };                         \
            mma16816(acc[0][2 * jj],     ar0, b0);                             \
            mma16816(acc[1][2 * jj],     ar1, b0);                             \
            mma16816(acc[0][2 * jj + 1], ar0, b1);                             \
            mma16816(acc[1][2 * jj + 1], ar1, b1);                             \
        }                                                                      \
    }                                                                          \
} while (0)

// GEMM1: h = gelu(x @ W1^T + b1) -> fp16 g_hh.  grid (24, E, 32)
__global__ void __launch_bounds__(256, 2)
gemm1_kernel(const float* __restrict__ bias)
{
    const int e = blockIdx.y;
    const int cnt = g_off[e + 1] - g_off[e];
    const int chunk = blockIdx.z;
    if (chunk * 4 >= cnt) return;
    const int m0 = blockIdx.x * BM;

    extern __shared__ __align__(16) char smem[];
    const uint32_t a_sp0 = smem_u32(smem);
    const uint32_t b_sp0 = a_sp0 + 2 * ASTG;

    const int tid = threadIdx.x;
    const int wid = tid >> 5, lane = tid & 31;
    const int wm = wid >> 1, wn = wid & 1;
    const int lg = lane >> 2, lt = lane & 3;

    int beamv[4];
#pragma unroll
    for (int j = 0; j < 4; j++) {
        int idx = chunk * 4 + j;
        beamv[j] = (idx < cnt) ? g_perm[g_off[e] + idx] : -1;
    }

    const int r0 = tid >> 2, c8 = (tid & 3) * 8;
    const __half* agp[2];
    const __half* bgp[2];
    agp[0] = g_w1h + (size_t)e * DFF_ * H_ + (size_t)(m0 + r0) * H_ + c8;
    agp[1] = agp[0] + (size_t)64 * H_;
#pragma unroll
    for (int t = 0; t < 2; t++) {
        int tok = r0 + 64 * t;
        int slot = tok >> 5, tt = tok & 31;
        int bm = beamv[slot]; if (bm < 0) bm = beamv[0];
        bgp[t] = g_xh + ((size_t)(bm >> 1) * T_ + tt) * H_ + c8;
    }
    const uint32_t a_spT = a_sp0 + (uint32_t)(r0 * STR_H + c8) * 2u;
    const uint32_t b_spT = b_sp0 + (uint32_t)(r0 * STR_H + c8) * 2u;

    const uint32_t a_base = a_sp0
        + (uint32_t)(((wm * 32 + (lane & 15)) * STR_H + ((lane >> 4) << 3)) << 1);
    const uint32_t b_base = b_sp0
        + (uint32_t)(((wn * 64 + ((lane >> 4) << 3) + (lane & 7)) * STR_H
                      + (((lane >> 3) & 1) << 3)) << 1);

    const int KT = H_ / BKT;   // 24

    { int bsel_p = 0; PREFETCH(0); }
    CP_COMMIT();

    float acc[2][8][4];
#pragma unroll
    for (int i = 0; i < 2; i++)
#pragma unroll
        for (int j = 0; j < 8; j++)
#pragma unroll
            for (int r = 0; r < 4; r++) acc[i][j][r] = 0.f;

#pragma unroll 1
    for (int kt = 0; kt < KT; kt++) {
        CP_WAIT0();
        __syncthreads();
        if (kt + 1 < KT) {
            int bsel_p = (kt + 1) & 1;
            PREFETCH((kt + 1) * BKT);
        }
        CP_COMMIT();
        KTILE_COMPUTE(kt & 1);
    }

    // epilogue: gelu(+bias) -> fp16
#pragma unroll
    for (int i = 0; i < 2; i++) {
        int rr0 = wm * 32 + i * 16 + lg, rr1 = rr0 + 8;
        int gm0 = m0 + rr0, gm1 = m0 + rr1;
        float bi0 = bias[e * DFF_ + gm0];
        float bi1 = bias[e * DFF_ + gm1];
#pragma unroll
        for (int j = 0; j < 8; j++) {
            int tok = wn * 64 + j * 8 + lt * 2;
            int bm = beamv[tok >> 5];
            if (bm < 0) continue;
            int tt = tok & 31;
            __half* p = g_hh + ((size_t)bm * T_ + tt) * DFF_;
            p[gm0]        = __float2half_rn(gelu_exact(acc[i][j][0] + bi0));
            p[DFF_ + gm0] = __float2half_rn(gelu_exact(acc[i][j][1] + bi0));
            p[gm1]        = __float2half_rn(gelu_exact(acc[i][j][2] + bi1));
            p[DFF_ + gm1] = __float2half_rn(gelu_exact(acc[i][j][3] + bi1));
        }
    }
}

// GEMM2 split-K (SPLIT=2): partial = h @ W2^T -> fp32 g_part. grid (6, E, 32*SPLIT)
__global__ void __launch_bounds__(256, 2)
gemm2_kernel(void)
{
    const int e = blockIdx.y;
    const int cnt = g_off[e + 1] - g_off[e];
    const int chunk = blockIdx.z / SPLIT;
    const int split = blockIdx.z % SPLIT;
    if (chunk * 4 >= cnt) return;
    const int m0 = blockIdx.x * BM;
    const int k0 = split * (DFF_ / SPLIT);

    extern __shared__ __align__(16) char smem[];
    const uint32_t a_sp0 = smem_u32(smem);
    const uint32_t b_sp0 = a_sp0 + 2 * ASTG;

    const int tid = threadIdx.x;
    const int wid = tid >> 5, lane = tid & 31;
    const int wm = wid >> 1, wn = wid & 1;
    const int lg = lane >> 2, lt = lane & 3;

    int beamv[4];
#pragma unroll
    for (int j = 0; j < 4; j++) {
        int idx = chunk * 4 + j;
        beamv[j] = (idx < cnt) ? g_perm[g_off[e] + idx] : -1;
    }

    const int r0 = tid >> 2, c8 = (tid & 3) * 8;
    const __half* agp[2];
    const __half* bgp[2];
    agp[0] = g_w2h + (size_t)e * H_ * DFF_ + (size_t)(m0 + r0) * DFF_ + k0 + c8;
    agp[1] = agp[0] + (size_t)64 * DFF_;
#pragma unroll
    for (int t = 0; t < 2; t++) {
        int tok = r0 + 64 * t;
        int slot = tok >> 5, tt = tok & 31;
        int bm = beamv[slot]; if (bm < 0) bm = beamv[0];
        bgp[t] = g_hh + ((size_t)bm * T_ + tt) * DFF_ + k0 + c8;
    }
    const uint32_t a_spT = a_sp0 + (uint32_t)(r0 * STR_H + c8) * 2u;
    const uint32_t b_spT = b_sp0 + (uint32_t)(r0 * STR_H + c8) * 2u;

    const uint32_t a_base = a_sp0
        + (uint32_t)(((wm * 32 + (lane & 15)) * STR_H + ((lane >> 4) << 3)) << 1);
    const uint32_t b_base = b_sp0
        + (uint32_t)(((wn * 64 + ((lane >> 4) << 3) + (lane & 7)) * STR_H
                      + (((lane >> 3) & 1) << 3)) << 1);

    const int KT = (DFF_ / SPLIT) / BKT;   // 48

    { int bsel_p = 0; PREFETCH(0); }
    CP_COMMIT();

    float acc[2][8][4];
#pragma unroll
    for (int i = 0; i < 2; i++)
#pragma unroll
        for (int j = 0; j < 8; j++)
#pragma unroll
            for (int r = 0; r < 4; r++) acc[i][j][r] = 0.f;

#pragma unroll 1
    for (int kt = 0; kt < KT; kt++) {
        CP_WAIT0();
        __syncthreads();
        if (kt + 1 < KT) {
            int bsel_p = (kt + 1) & 1;
            PREFETCH((kt + 1) * BKT);
        }
        CP_COMMIT();
        KTILE_COMPUTE(kt & 1);
    }

    // epilogue: raw fp32 partials
#pragma unroll
    for (int i = 0; i < 2; i++) {
        int rr0 = wm * 32 + i * 16 + lg, rr1 = rr0 + 8;
        int gm0 = m0 + rr0, gm1 = m0 + rr1;
        float* pb = g_part + (size_t)split * NBEAM * T_ * H_;
#pragma unroll
        for (int j = 0; j < 8; j++) {
            int tok = wn * 64 + j * 8 + lt * 2;
            int bm = beamv[tok >> 5];
            if (bm < 0) continue;
            int tt = tok & 31;
            float* p = pb + ((size_t)bm * T_ + tt) * H_;
            p[gm0]      = acc[i][j][0];
            p[H_ + gm0] = acc[i][j][1];
            p[gm1]      = acc[i][j][2];
            p[H_ + gm1] = acc[i][j][3];
        }
    }
}

// Reduce: out = (sum of SPLIT partials + b2[e]) * wgt
__global__ void reduce_kernel(const float* __restrict__ b2, float* __restrict__ out)
{
    int i = blockIdx.x * blockDim.x + threadIdx.x;
    const int N4 = NBEAM * T_ * H_ / 4;
    if (i >= N4) return;
    int flat = i * 4;
    int beam = flat / (T_ * H_);
    int hh   = flat % H_;
    int e    = g_expert[beam];
    float wgt = g_weight[beam];
    const size_t PS = (size_t)NBEAM * T_ * H_;
    float4 s  = ((const float4*)g_part)[i];
    float4 p1 = ((const float4*)(g_part + PS))[i];
    float4 bbv = *(const float4*)(b2 + e * H_ + hh);
    float4 o;
    o.x = (s.x + p1.x + bbv.x) * wgt;
    o.y = (s.y + p1.y + bbv.y) * wgt;
    o.z = (s.z + p1.z + bbv.z) * wgt;
    o.w = (s.w + p1.w + bbv.w) * wgt;
    ((float4*)(out + OUT_MAIN))[i] = o;
}

// ---------------------------------------------------------------------------
extern "C" void kernel_launch(void* const* d_in, const int* in_sizes, int n_in,
                              void* d_out, int out_size)
{
    (void)in_sizes; (void)n_in; (void)out_size;
    const float* x      = (const float*)d_in[0];
    const float* gate_w = (const float*)d_in[1];
    const float* w1     = (const float*)d_in[2];
    const float* b1     = (const float*)d_in[3];
    const float* w2     = (const float*)d_in[4];
    const float* b2     = (const float*)d_in[5];
    float* out = (float*)d_out;

    // One-time setup (no device memory allocation; streams/events are host objects)
    static cudaStream_t sW1 = nullptr, sW2 = nullptr;
    static cudaEvent_t evRoot = nullptr, evW1 = nullptr, evW2 = nullptr;
    if (sW1 == nullptr) {
        cudaStreamCreateWithFlags(&sW1, cudaStreamNonBlocking);
        cudaStreamCreateWithFlags(&sW2, cudaStreamNonBlocking);
        cudaEventCreateWithFlags(&evRoot, cudaEventDisableTiming);
        cudaEventCreateWithFlags(&evW1, cudaEventDisableTiming);
        cudaEventCreateWithFlags(&evW2, cudaEventDisableTiming);
        cudaFuncSetAttribute(gemm1_kernel,
            cudaFuncAttributeMaxDynamicSharedMemorySize, SMEM_BYTES);
        cudaFuncSetAttribute(gemm2_kernel,
            cudaFuncAttributeMaxDynamicSharedMemorySize, SMEM_BYTES);
    }

    const int NW4 = E_ * DFF_ * H_ / 4;        // 4718592

    // Fork: weight conversions on side streams
    cudaEventRecord(evRoot, 0);
    cudaStreamWaitEvent(sW1, evRoot, 0);
    cudaStreamWaitEvent(sW2, evRoot, 0);

    prep_h_kernel<<<(NW4 + 255) / 256, 256, 0, sW1>>>(w1, 1, NW4);
    cudaEventRecord(evW1, sW1);
    prep_h_kernel<<<(NW4 + 255) / 256, 256, 0, sW2>>>(w2, 2, NW4);
    cudaEventRecord(evW2, sW2);

    // Main stream: fused gate (emits g_xh + logits) -> finalize
    gate_fused_kernel<<<B_, 192>>>(x, gate_w);
    finalize_kernel<<<1, 128>>>(out);

    // Join w1 before GEMM1
    cudaStreamWaitEvent(0, evW1, 0);
    gemm1_kernel<<<dim3(DFF_ / BM, E_, 32), 256, SMEM_BYTES>>>(b1);

    // Join w2 before GEMM2 (prep_w2 overlapped with gate/finalize/gemm1)
    cudaStreamWaitEvent(0, evW2, 0);
    gemm2_kernel<<<dim3(H_ / BM, E_, 32 * SPLIT), 256, SMEM_BYTES>>>();
    reduce_kernel<<<(NBEAM * T_ * H_ / 4 + 255) / 256, 256>>>(b2, out);
}